// round 15
// baseline (speedup 1.0000x reference)
#include <cuda_runtime.h>
#include <cuda_fp16.h>
#include <cstdint>

constexpr int M = 1024;
constexpr int N = 32768;
constexpr int K = 512;
constexpr float MARGIN = 0.3f;

constexpr int BM = 128, BN = 256, BK = 64;
constexpr int NCH = K / BK;              // 8
constexpr int ROWB = 128;                // 64 f16 = 128B row, SW128 swizzle

// dynamic smem layout (double buffered, SW128)
constexpr uint32_t OFF_LAB = 0;                          // 256 ints = 1KB
constexpr uint32_t OFF_A   = 1024;
constexpr uint32_t A_STAGE = BM * ROWB;                  // 16384
constexpr uint32_t OFF_B   = OFF_A + 2 * A_STAGE;        // 33792
constexpr uint32_t B_STAGE = BN * ROWB;                  // 32768
constexpr uint32_t SMEM_TOTAL = OFF_B + 2 * B_STAGE;     // 99328 (x2 CTAs/SM)

__device__ unsigned g_posU[M];
__device__ unsigned g_negU[M];
__device__ unsigned g_ctr;
__device__ __half g_Ah[M * K];
__device__ __half g_Bh[(size_t)N * K];

__device__ __forceinline__ float f_inf()  { return __int_as_float(0x7f800000); }
__device__ __forceinline__ float f_ninf() { return __int_as_float(0xff800000); }

__device__ __forceinline__ unsigned encOrd(float f) {
    unsigned b = __float_as_uint(f);
    return (b & 0x80000000u) ? ~b : (b | 0x80000000u);
}
__device__ __forceinline__ float decOrd(unsigned u) {
    return (u & 0x80000000u) ? __uint_as_float(u ^ 0x80000000u)
                             : __uint_as_float(~u);
}

__device__ __forceinline__ uint32_t swz(uint32_t b) { return b ^ ((b >> 3) & 0x70); }

__device__ __forceinline__ uint32_t smem_u32(const void* p) {
    uint32_t a;
    asm("{ .reg .u64 t; cvta.to.shared.u64 t, %1; cvt.u32.u64 %0, t; }" : "=r"(a) : "l"(p));
    return a;
}
__device__ __forceinline__ void ldsm_x4(uint32_t* r, uint32_t addr) {
    asm volatile("ldmatrix.sync.aligned.m8n8.x4.shared.b16 {%0,%1,%2,%3}, [%4];"
                 : "=r"(r[0]), "=r"(r[1]), "=r"(r[2]), "=r"(r[3]) : "r"(addr));
}
__device__ __forceinline__ void mma_f16(uint32_t* d, const uint32_t* a, const uint32_t* b) {
    asm volatile(
        "mma.sync.aligned.m16n8k16.row.col.f16.f16.f16.f16 "
        "{%0,%1}, {%2,%3,%4,%5}, {%6,%7}, {%0,%1};"
        : "+r"(d[0]), "+r"(d[1])
        : "r"(a[0]), "r"(a[1]), "r"(a[2]), "r"(a[3]), "r"(b[0]), "r"(b[1]));
}
// cp.async with compile-time dst/src byte offsets folded into the address.
template <int DOFF, int SOFF>
__device__ __forceinline__ void cp_async16_o(uint32_t dst, const void* src) {
    asm volatile("cp.async.cg.shared.global [%0+%2], [%1+%3], 16;"
                 :: "r"(dst), "l"(src), "n"(DOFF), "n"(SOFF));
}
__device__ __forceinline__ void cp_commit() {
    asm volatile("cp.async.commit_group;" ::: "memory");
}
template <int NG> __device__ __forceinline__ void cp_wait() {
    asm volatile("cp.async.wait_group %0;" :: "n"(NG) : "memory");
}

// fp32 -> f16 scratch (streaming), plus min/max array init.
__global__ void tl_quant(const float* __restrict__ A, const float* __restrict__ B) {
    const int gid = blockIdx.x * blockDim.x + threadIdx.x;
    const int nth = gridDim.x * blockDim.x;
    if (gid < M) { g_posU[gid] = 0xFFFFFFFFu; g_negU[gid] = 0u; }

    auto pack8 = [](float4 a, float4 b) {
        __half2 h0 = __floats2half2_rn(a.x, a.y);
        __half2 h1 = __floats2half2_rn(a.z, a.w);
        __half2 h2 = __floats2half2_rn(b.x, b.y);
        __half2 h3 = __floats2half2_rn(b.z, b.w);
        return make_uint4(*(uint32_t*)&h0, *(uint32_t*)&h1,
                          *(uint32_t*)&h2, *(uint32_t*)&h3);
    };

    for (int i = gid; i < M * K / 8; i += nth) {
        const float4* src = reinterpret_cast<const float4*>(A) + 2 * (size_t)i;
        float4 v0 = __ldcs(src), v1 = __ldcs(src + 1);
        __stcs(reinterpret_cast<uint4*>(g_Ah) + i, pack8(v0, v1));
    }
#pragma unroll 4
    for (size_t i = gid; i < (size_t)N * K / 8; i += nth) {
        const float4* src = reinterpret_cast<const float4*>(B) + 2 * i;
        float4 v0 = __ldcs(src), v1 = __ldcs(src + 1);
        __stcs(reinterpret_cast<uint4*>(g_Bh) + i, pack8(v0, v1));
    }
}

__global__ __launch_bounds__(256, 2)
void tl_gemm(const int* __restrict__ targets, const int* __restrict__ idxv,
             const int* __restrict__ labels, float* __restrict__ out)
{
    extern __shared__ __align__(1024) char smem[];
    __shared__ int      sT[BM];
    __shared__ int      sI[BM];
    __shared__ unsigned sPosU[BM];
    __shared__ unsigned sNegU[BM];
    __shared__ float    sRed[8];
    __shared__ unsigned sIsLast;

    const uint32_t sb = smem_u32(smem);
    const uint32_t sA = sb + OFF_A;
    const uint32_t sB = sb + OFF_B;
    int* sLab = (int*)(smem + OFF_LAB);

    const int tid  = threadIdx.x;
    const int lane = tid & 31;
    const int wid  = tid >> 5;
    const int rowBase = blockIdx.y * BM;
    const int colBase = blockIdx.x * BN;

    // 8 warps: 2 (m) x 4 (n); warp tile 64 x 64
    const int warp_m = (wid >> 2) * 64;
    const int warp_n = (wid & 3) * 64;

    // Loader geometry: q = tid&7 (k-offset, invariant), row = (tid>>3) + 32*i.
    // Per-i deltas are immediates: smem +4096 (swizzle-commuting), gmem +32768B.
    const int r0 = tid >> 3;
    const int q16 = (tid & 7) * 16;                          // byte offset in row
    const uint32_t dstSwz = swz((uint32_t)(r0 * ROWB) + q16); // shared A/B dst base
    const __half* aSrc0 = g_Ah + (size_t)(rowBase + r0) * K + (tid & 7) * 8;
    const __half* bSrc0 = g_Bh + (size_t)(colBase + r0) * K + (tid & 7) * 8;

    // Issue chunk-0 loads FIRST (latency head start), then scalar prologue.
    {
        const uint32_t dA = sA + dstSwz, dB = sB + dstSwz;
        cp_async16_o<0,      0>(dA, aSrc0);
        cp_async16_o<4096,   32768>(dA, aSrc0);
        cp_async16_o<8192,   65536>(dA, aSrc0);
        cp_async16_o<12288,  98304>(dA, aSrc0);
        cp_async16_o<0,      0>(dB, bSrc0);
        cp_async16_o<4096,   32768>(dB, bSrc0);
        cp_async16_o<8192,   65536>(dB, bSrc0);
        cp_async16_o<12288,  98304>(dB, bSrc0);
        cp_async16_o<16384, 131072>(dB, bSrc0);
        cp_async16_o<20480, 163840>(dB, bSrc0);
        cp_async16_o<24576, 196608>(dB, bSrc0);
        cp_async16_o<28672, 229376>(dB, bSrc0);
        cp_commit();
    }

    for (int i = tid; i < BN; i += 256) sLab[i] = labels[colBase + i];
    if (tid < BM) {
        sT[tid] = targets[rowBase + tid];
        sI[tid] = idxv[rowBase + tid];
        sPosU[tid] = 0xFFFFFFFFu;
        sNegU[tid] = 0u;
    }

    // Hoisted, pre-swizzled ldmatrix offsets (stage-relative).
    uint32_t aB[4], bB[4];
#pragma unroll
    for (int mi = 0; mi < 4; ++mi)
        aB[mi] = swz((uint32_t)(warp_m + (lane & 15) + mi * 16) * ROWB
                     + (lane >> 4) * 16);
#pragma unroll
    for (int g = 0; g < 4; ++g)
        bB[g] = swz((uint32_t)(warp_n + (lane & 7) + ((lane >> 4) & 1) * 8 + g * 16) * ROWB
                    + ((lane >> 3) & 1) * 16);

    uint32_t acc[4][8][2] = {};   // f16x2 accumulators

#pragma unroll 2
    for (int c = 0; c < NCH; ++c) {
        cp_wait<0>();
        __syncthreads();
        if (c + 1 < NCH) {
            // Refill the buffer consumed during chunk c-1 with chunk c+1.
            const uint32_t dA = sA + ((c + 1) & 1) * A_STAGE + dstSwz;
            const uint32_t dB = sB + ((c + 1) & 1) * B_STAGE + dstSwz;
            const __half* aS = aSrc0 + (c + 1) * BK;
            const __half* bS = bSrc0 + (c + 1) * BK;
            cp_async16_o<0,      0>(dA, aS);
            cp_async16_o<4096,   32768>(dA, aS);
            cp_async16_o<8192,   65536>(dA, aS);
            cp_async16_o<12288,  98304>(dA, aS);
            cp_async16_o<0,      0>(dB, bS);
            cp_async16_o<4096,   32768>(dB, bS);
            cp_async16_o<8192,   65536>(dB, bS);
            cp_async16_o<12288,  98304>(dB, bS);
            cp_async16_o<16384, 131072>(dB, bS);
            cp_async16_o<20480, 163840>(dB, bS);
            cp_async16_o<24576, 196608>(dB, bS);
            cp_async16_o<28672, 229376>(dB, bS);
            cp_commit();
        }

        // Fold the stage base into the hoisted offsets (base 1024-aligned:
        // the ks XOR (bits 5-6) cannot carry-interact with the add).
        const uint32_t stA = sA + (c & 1) * A_STAGE;
        const uint32_t stB = sB + (c & 1) * B_STAGE;
        uint32_t aBs[4], bBs[4];
#pragma unroll
        for (int mi = 0; mi < 4; ++mi) aBs[mi] = stA + aB[mi];
#pragma unroll
        for (int g = 0; g < 4; ++g)    bBs[g] = stB + bB[g];

#pragma unroll
        for (int ks = 0; ks < 4; ++ks) {
            const uint32_t kx = (uint32_t)ks << 5;
            uint32_t af[4][4], bfr[4][4];
#pragma unroll
            for (int mi = 0; mi < 4; ++mi)
                ldsm_x4(af[mi], aBs[mi] ^ kx);
#pragma unroll
            for (int g = 0; g < 4; ++g)
                ldsm_x4(bfr[g], bBs[g] ^ kx);
#pragma unroll
            for (int mi = 0; mi < 4; ++mi)
#pragma unroll
                for (int ni = 0; ni < 8; ++ni)
                    mma_f16(acc[mi][ni], af[mi], &bfr[ni >> 1][(ni & 1) * 2]);
        }
    }
    __syncthreads();

    // Epilogue: unpack f16 acc, masked min/max with ordered-uint atomics.
    const int lq = lane >> 2;
    const int lr = (lane & 3) * 2;
#pragma unroll
    for (int mi = 0; mi < 4; ++mi) {
#pragma unroll
        for (int h = 0; h < 2; ++h) {
            const int rloc = warp_m + mi * 16 + h * 8 + lq;
            const int tg = sT[rloc];
            const int ix = sI[rloc];
            float pmin = f_inf(), nmax = f_ninf();
#pragma unroll
            for (int ni = 0; ni < 8; ++ni) {
                const float2 f2 = __half22float2(
                    *reinterpret_cast<const __half2*>(&acc[mi][ni][h]));
#pragma unroll
                for (int j = 0; j < 2; ++j) {
                    const int cloc = warp_n + ni * 8 + lr + j;
                    const float v = (j == 0) ? f2.x : f2.y;
                    if (sLab[cloc] == tg) {
                        if (colBase + cloc != ix) pmin = fminf(pmin, v);
                    } else {
                        nmax = fmaxf(nmax, v);
                    }
                }
            }
            if (pmin <  f_inf())  atomicMin(&sPosU[rloc], encOrd(pmin));
            if (nmax > f_ninf())  atomicMax(&sNegU[rloc], encOrd(nmax));
        }
    }
    __syncthreads();

    if (tid < BM) {
        const unsigned p = sPosU[tid], q = sNegU[tid];
        if (p != 0xFFFFFFFFu) atomicMin(&g_posU[rowBase + tid], p);
        if (q != 0u)          atomicMax(&g_negU[rowBase + tid], q);
    }

    // ---- fused finale ----
    __threadfence();
    if (tid == 0) {
        const unsigned total = gridDim.x * gridDim.y;
        sIsLast = (atomicAdd(&g_ctr, 1u) == total - 1u);
    }
    __syncthreads();
    if (!sIsLast) return;

    __threadfence();
    float l = 0.f;
#pragma unroll
    for (int r = 0; r < 4; ++r) {
        const int row = tid + r * 256;
        const float pos = decOrd(__ldcg(&g_posU[row]));
        const float neg = decOrd(__ldcg(&g_negU[row]));
        l += fmaxf(neg - pos + MARGIN, 0.0f);
    }
#pragma unroll
    for (int o = 16; o > 0; o >>= 1) l += __shfl_xor_sync(0xffffffffu, l, o);
    if (lane == 0) sRed[wid] = l;
    __syncthreads();
    if (tid < 8) {
        float s = sRed[tid];
#pragma unroll
        for (int o = 4; o > 0; o >>= 1) s += __shfl_xor_sync(0xffu, s, o);
        if (tid == 0) {
            out[0] = s * (1.0f / (float)M);
            g_ctr = 0;
        }
    }
}

extern "C" void kernel_launch(void* const* d_in, const int* in_sizes, int n_in,
                              void* d_out, int out_size) {
    const float* A       = (const float*)d_in[0];
    const float* B       = (const float*)d_in[1];
    const int*   targets = (const int*)  d_in[2];
    const int*   idxv    = (const int*)  d_in[3];
    const int*   labels  = (const int*)  d_in[4];
    float*       out     = (float*)d_out;

    static bool attrSet = false;
    if (!attrSet) {
        cudaFuncSetAttribute(tl_gemm, cudaFuncAttributeMaxDynamicSharedMemorySize,
                             SMEM_TOTAL);
        attrSet = true;
    }

    tl_quant<<<1024, 256>>>(A, B);
    dim3 grid(N / BN, M / BM);   // 128 x 8 = 1024 CTAs
    tl_gemm<<<grid, 256, SMEM_TOTAL>>>(targets, idxv, labels, out);
}

// round 16
// speedup vs baseline: 1.0196x; 1.0196x over previous
#include <cuda_runtime.h>
#include <cuda_fp16.h>
#include <cstdint>

constexpr int M = 1024;
constexpr int N = 32768;
constexpr int K = 512;
constexpr float MARGIN = 0.3f;

constexpr int BM = 128, BN = 128, BK = 64;
constexpr int NCH = K / BK;              // 8
constexpr int ROWB = 128;                // 64 f16 = 128B row, SW128 swizzle

// dynamic smem layout (double buffered, SW128)
constexpr uint32_t OFF_LAB = 0;                          // 128 ints
constexpr uint32_t OFF_A   = 1024;
constexpr uint32_t A_STAGE = BM * ROWB;                  // 16384
constexpr uint32_t OFF_B   = OFF_A + 2 * A_STAGE;        // 33792
constexpr uint32_t B_STAGE = BN * ROWB;                  // 16384
constexpr uint32_t SMEM_TOTAL = OFF_B + 2 * B_STAGE;     // 66560 (x3 CTAs/SM)

__device__ unsigned g_posU[M];
__device__ unsigned g_negU[M];
__device__ unsigned g_ctr;
__device__ __half g_Ah[M * K];
__device__ __half g_Bh[(size_t)N * K];

__device__ __forceinline__ float f_inf()  { return __int_as_float(0x7f800000); }
__device__ __forceinline__ float f_ninf() { return __int_as_float(0xff800000); }

__device__ __forceinline__ unsigned encOrd(float f) {
    unsigned b = __float_as_uint(f);
    return (b & 0x80000000u) ? ~b : (b | 0x80000000u);
}
__device__ __forceinline__ float decOrd(unsigned u) {
    return (u & 0x80000000u) ? __uint_as_float(u ^ 0x80000000u)
                             : __uint_as_float(~u);
}

__device__ __forceinline__ uint32_t swz(uint32_t b) { return b ^ ((b >> 3) & 0x70); }

__device__ __forceinline__ uint32_t smem_u32(const void* p) {
    uint32_t a;
    asm("{ .reg .u64 t; cvta.to.shared.u64 t, %1; cvt.u32.u64 %0, t; }" : "=r"(a) : "l"(p));
    return a;
}
__device__ __forceinline__ void ldsm_x4(uint32_t* r, uint32_t addr) {
    asm volatile("ldmatrix.sync.aligned.m8n8.x4.shared.b16 {%0,%1,%2,%3}, [%4];"
                 : "=r"(r[0]), "=r"(r[1]), "=r"(r[2]), "=r"(r[3]) : "r"(addr));
}
__device__ __forceinline__ void mma_f16(uint32_t* d, const uint32_t* a, const uint32_t* b) {
    asm volatile(
        "mma.sync.aligned.m16n8k16.row.col.f16.f16.f16.f16 "
        "{%0,%1}, {%2,%3,%4,%5}, {%6,%7}, {%0,%1};"
        : "+r"(d[0]), "+r"(d[1])
        : "r"(a[0]), "r"(a[1]), "r"(a[2]), "r"(a[3]), "r"(b[0]), "r"(b[1]));
}
__device__ __forceinline__ void cp_async16(uint32_t dst, const void* src) {
    asm volatile("cp.async.cg.shared.global [%0], [%1], 16;" :: "r"(dst), "l"(src));
}
__device__ __forceinline__ void cp_commit() {
    asm volatile("cp.async.commit_group;" ::: "memory");
}
template <int NG> __device__ __forceinline__ void cp_wait() {
    asm volatile("cp.async.wait_group %0;" :: "n"(NG) : "memory");
}

// fp32 -> f16 scratch (streaming), plus min/max array init.
__global__ void tl_quant(const float* __restrict__ A, const float* __restrict__ B) {
    const int gid = blockIdx.x * blockDim.x + threadIdx.x;
    const int nth = gridDim.x * blockDim.x;
    if (gid < M) { g_posU[gid] = 0xFFFFFFFFu; g_negU[gid] = 0u; }

    auto pack8 = [](float4 a, float4 b) {
        __half2 h0 = __floats2half2_rn(a.x, a.y);
        __half2 h1 = __floats2half2_rn(a.z, a.w);
        __half2 h2 = __floats2half2_rn(b.x, b.y);
        __half2 h3 = __floats2half2_rn(b.z, b.w);
        return make_uint4(*(uint32_t*)&h0, *(uint32_t*)&h1,
                          *(uint32_t*)&h2, *(uint32_t*)&h3);
    };

    for (int i = gid; i < M * K / 8; i += nth) {
        const float4* src = reinterpret_cast<const float4*>(A) + 2 * (size_t)i;
        float4 v0 = __ldcs(src), v1 = __ldcs(src + 1);
        __stcs(reinterpret_cast<uint4*>(g_Ah) + i, pack8(v0, v1));
    }
#pragma unroll 4
    for (size_t i = gid; i < (size_t)N * K / 8; i += nth) {
        const float4* src = reinterpret_cast<const float4*>(B) + 2 * i;
        float4 v0 = __ldcs(src), v1 = __ldcs(src + 1);
        __stcs(reinterpret_cast<uint4*>(g_Bh) + i, pack8(v0, v1));
    }
}

__global__ __launch_bounds__(256, 3)
void tl_gemm(const int* __restrict__ targets, const int* __restrict__ idxv,
             const int* __restrict__ labels, float* __restrict__ out)
{
    extern __shared__ __align__(1024) char smem[];
    __shared__ int      sT[BM];
    __shared__ int      sI[BM];
    __shared__ unsigned sPosU[BM];
    __shared__ unsigned sNegU[BM];
    __shared__ float    sRed[8];
    __shared__ unsigned sIsLast;

    const uint32_t sb = smem_u32(smem);
    const uint32_t sA = sb + OFF_A;
    const uint32_t sB = sb + OFF_B;
    int* sLab = (int*)(smem + OFF_LAB);

    const int tid  = threadIdx.x;
    const int lane = tid & 31;
    const int wid  = tid >> 5;
    const int rowBase = blockIdx.y * BM;
    const int colBase = blockIdx.x * BN;

    // 8 warps: 2 (m) x 4 (n); warp tile 64 x 32
    const int warp_m = (wid >> 2) * 64;
    const int warp_n = (wid & 3) * 32;

    for (int i = tid; i < BN; i += 256) sLab[i] = labels[colBase + i];
    if (tid < BM) {
        sT[tid] = targets[rowBase + tid];
        sI[tid] = idxv[rowBase + tid];
        sPosU[tid] = 0xFFFFFFFFu;
        sNegU[tid] = 0u;
    }

    // stage loader: A and B each 128 rows x 8 x 16B chunks = 1024 -> 4/thread
    auto load_stage = [&](int st, int c) {
        const int kb = c * BK;
        const uint32_t dA = sA + st * A_STAGE;
        const uint32_t dB = sB + st * B_STAGE;
#pragma unroll
        for (int i = 0; i < 4; ++i) {
            const int v = tid + i * 256;
            const int r = v >> 3, q = v & 7;
            cp_async16(dA + swz((uint32_t)(r * ROWB + q * 16)),
                       g_Ah + (size_t)(rowBase + r) * K + kb + q * 8);
        }
#pragma unroll
        for (int i = 0; i < 4; ++i) {
            const int v = tid + i * 256;
            const int r = v >> 3, q = v & 7;
            cp_async16(dB + swz((uint32_t)(r * ROWB + q * 16)),
                       g_Bh + (size_t)(colBase + r) * K + kb + q * 8);
        }
        cp_commit();
    };

    // Hoisted, pre-swizzled ldmatrix base addresses.
    // Identity: swz(base + ks*32) == swz(base) ^ (ks<<5)
    uint32_t aB[4], bB[2];
#pragma unroll
    for (int mi = 0; mi < 4; ++mi)
        aB[mi] = swz((uint32_t)(warp_m + (lane & 15) + mi * 16) * ROWB
                     + (lane >> 4) * 16);
#pragma unroll
    for (int g = 0; g < 2; ++g)
        bB[g] = swz((uint32_t)(warp_n + (lane & 7) + ((lane >> 4) & 1) * 8 + g * 16) * ROWB
                    + ((lane >> 3) & 1) * 16);

    uint32_t acc[4][4][2] = {};   // f16x2 accumulators (32 regs)

    load_stage(0, 0);             // prologue: only chunk 0

#pragma unroll 1
    for (int c = 0; c < NCH; ++c) {
        cp_wait<0>();
        __syncthreads();
        if (c + 1 < NCH) load_stage((c + 1) & 1, c + 1);

        const uint32_t stA = sA + (c & 1) * A_STAGE;
        const uint32_t stB = sB + (c & 1) * B_STAGE;
#pragma unroll
        for (int ks = 0; ks < 4; ++ks) {
            const uint32_t kx = (uint32_t)ks << 5;
            uint32_t af[4][4], bfr[2][4];
#pragma unroll
            for (int mi = 0; mi < 4; ++mi)
                ldsm_x4(af[mi], stA + (aB[mi] ^ kx));
#pragma unroll
            for (int g = 0; g < 2; ++g)
                ldsm_x4(bfr[g], stB + (bB[g] ^ kx));
#pragma unroll
            for (int mi = 0; mi < 4; ++mi)
#pragma unroll
                for (int ni = 0; ni < 4; ++ni)
                    mma_f16(acc[mi][ni], af[mi], &bfr[ni >> 1][(ni & 1) * 2]);
        }
    }
    __syncthreads();

    // Epilogue: unpack f16 acc, masked min/max with ordered-uint atomics.
    const int lq = lane >> 2;
    const int lr = (lane & 3) * 2;
#pragma unroll
    for (int mi = 0; mi < 4; ++mi) {
#pragma unroll
        for (int h = 0; h < 2; ++h) {
            const int rloc = warp_m + mi * 16 + h * 8 + lq;
            const int tg = sT[rloc];
            const int ix = sI[rloc];
            float pmin = f_inf(), nmax = f_ninf();
#pragma unroll
            for (int ni = 0; ni < 4; ++ni) {
                const float2 f2 = __half22float2(
                    *reinterpret_cast<const __half2*>(&acc[mi][ni][h]));
#pragma unroll
                for (int j = 0; j < 2; ++j) {
                    const int cloc = warp_n + ni * 8 + lr + j;
                    const float v = (j == 0) ? f2.x : f2.y;
                    if (sLab[cloc] == tg) {
                        if (colBase + cloc != ix) pmin = fminf(pmin, v);
                    } else {
                        nmax = fmaxf(nmax, v);
                    }
                }
            }
            if (pmin <  f_inf())  atomicMin(&sPosU[rloc], encOrd(pmin));
            if (nmax > f_ninf())  atomicMax(&sNegU[rloc], encOrd(nmax));
        }
    }
    __syncthreads();

    if (tid < BM) {
        const unsigned p = sPosU[tid], q = sNegU[tid];
        if (p != 0xFFFFFFFFu) atomicMin(&g_posU[rowBase + tid], p);
        if (q != 0u)          atomicMax(&g_negU[rowBase + tid], q);
    }

    // ---- fused finale ----
    __threadfence();
    if (tid == 0) {
        const unsigned total = gridDim.x * gridDim.y;
        sIsLast = (atomicAdd(&g_ctr, 1u) == total - 1u);
    }
    __syncthreads();
    if (!sIsLast) return;

    __threadfence();
    float l = 0.f;
#pragma unroll
    for (int r = 0; r < 4; ++r) {
        const int row = tid + r * 256;
        const float pos = decOrd(__ldcg(&g_posU[row]));
        const float neg = decOrd(__ldcg(&g_negU[row]));
        l += fmaxf(neg - pos + MARGIN, 0.0f);
    }
#pragma unroll
    for (int o = 16; o > 0; o >>= 1) l += __shfl_xor_sync(0xffffffffu, l, o);
    if (lane == 0) sRed[wid] = l;
    __syncthreads();
    if (tid < 8) {
        float s = sRed[tid];
#pragma unroll
        for (int o = 4; o > 0; o >>= 1) s += __shfl_xor_sync(0xffu, s, o);
        if (tid == 0) {
            out[0] = s * (1.0f / (float)M);
            g_ctr = 0;
        }
    }
}

extern "C" void kernel_launch(void* const* d_in, const int* in_sizes, int n_in,
                              void* d_out, int out_size) {
    const float* A       = (const float*)d_in[0];
    const float* B       = (const float*)d_in[1];
    const int*   targets = (const int*)  d_in[2];
    const int*   idxv    = (const int*)  d_in[3];
    const int*   labels  = (const int*)  d_in[4];
    float*       out     = (float*)d_out;

    static bool attrSet = false;
    if (!attrSet) {
        cudaFuncSetAttribute(tl_gemm, cudaFuncAttributeMaxDynamicSharedMemorySize,
                             SMEM_TOTAL);
        attrSet = true;
    }

    tl_quant<<<1024, 256>>>(A, B);
    dim3 grid(N / BN, M / BM);   // 256 x 8 = 2048 CTAs
    tl_gemm<<<grid, 256, SMEM_TOTAL>>>(targets, idxv, labels, out);
}

// round 17
// speedup vs baseline: 1.0557x; 1.0354x over previous
#include <cuda_runtime.h>
#include <cuda_fp16.h>
#include <cstdint>

constexpr int M = 1024;
constexpr int N = 32768;
constexpr int K = 512;
constexpr float MARGIN = 0.3f;

constexpr int BM = 128, BN = 256, BK = 64;
constexpr int NCH = K / BK;              // 8
constexpr int ROWB = 128;                // 64 f16 = 128B row, SW128 swizzle

// dynamic smem layout (double buffered, SW128)
constexpr uint32_t OFF_LAB = 0;                          // 256 ints = 1KB
constexpr uint32_t OFF_A   = 1024;
constexpr uint32_t A_STAGE = BM * ROWB;                  // 16384
constexpr uint32_t OFF_B   = OFF_A + 2 * A_STAGE;        // 33792
constexpr uint32_t B_STAGE = BN * ROWB;                  // 32768
constexpr uint32_t SMEM_TOTAL = OFF_B + 2 * B_STAGE;     // 99328 (x2 CTAs/SM)

__device__ unsigned g_posU[M];
__device__ unsigned g_negU[M];
__device__ unsigned g_ctr;
__device__ __half g_Ah[M * K];
__device__ __half g_Bh[(size_t)N * K];

__device__ __forceinline__ float f_inf()  { return __int_as_float(0x7f800000); }
__device__ __forceinline__ float f_ninf() { return __int_as_float(0xff800000); }

__device__ __forceinline__ unsigned encOrd(float f) {
    unsigned b = __float_as_uint(f);
    return (b & 0x80000000u) ? ~b : (b | 0x80000000u);
}
__device__ __forceinline__ float decOrd(unsigned u) {
    return (u & 0x80000000u) ? __uint_as_float(u ^ 0x80000000u)
                             : __uint_as_float(~u);
}

__device__ __forceinline__ uint32_t swz(uint32_t b) { return b ^ ((b >> 3) & 0x70); }

__device__ __forceinline__ uint32_t smem_u32(const void* p) {
    uint32_t a;
    asm("{ .reg .u64 t; cvta.to.shared.u64 t, %1; cvt.u32.u64 %0, t; }" : "=r"(a) : "l"(p));
    return a;
}
__device__ __forceinline__ void ldsm_x4(uint32_t* r, uint32_t addr) {
    asm volatile("ldmatrix.sync.aligned.m8n8.x4.shared.b16 {%0,%1,%2,%3}, [%4];"
                 : "=r"(r[0]), "=r"(r[1]), "=r"(r[2]), "=r"(r[3]) : "r"(addr));
}
__device__ __forceinline__ void mma_f16(uint32_t* d, const uint32_t* a, const uint32_t* b) {
    asm volatile(
        "mma.sync.aligned.m16n8k16.row.col.f16.f16.f16.f16 "
        "{%0,%1}, {%2,%3,%4,%5}, {%6,%7}, {%0,%1};"
        : "+r"(d[0]), "+r"(d[1])
        : "r"(a[0]), "r"(a[1]), "r"(a[2]), "r"(a[3]), "r"(b[0]), "r"(b[1]));
}
__device__ __forceinline__ void cp_async16(uint32_t dst, const void* src) {
    asm volatile("cp.async.cg.shared.global [%0], [%1], 16;" :: "r"(dst), "l"(src));
}
__device__ __forceinline__ void cp_commit() {
    asm volatile("cp.async.commit_group;" ::: "memory");
}
template <int NG> __device__ __forceinline__ void cp_wait() {
    asm volatile("cp.async.wait_group %0;" :: "n"(NG) : "memory");
}

// fp32 -> f16 scratch. Reads: streaming (__ldcs, dead after this kernel).
// Writes: __stcg (NORMAL policy) so the f16 arrays stay L2-resident for the
// GEMM's first wave (65MB < 126MB L2). Also inits the min/max arrays.
__global__ void tl_quant(const float* __restrict__ A, const float* __restrict__ B) {
    const int gid = blockIdx.x * blockDim.x + threadIdx.x;
    const int nth = gridDim.x * blockDim.x;
    if (gid < M) { g_posU[gid] = 0xFFFFFFFFu; g_negU[gid] = 0u; }

    auto pack8 = [](float4 a, float4 b) {
        __half2 h0 = __floats2half2_rn(a.x, a.y);
        __half2 h1 = __floats2half2_rn(a.z, a.w);
        __half2 h2 = __floats2half2_rn(b.x, b.y);
        __half2 h3 = __floats2half2_rn(b.z, b.w);
        return make_uint4(*(uint32_t*)&h0, *(uint32_t*)&h1,
                          *(uint32_t*)&h2, *(uint32_t*)&h3);
    };

    for (int i = gid; i < M * K / 8; i += nth) {
        const float4* src = reinterpret_cast<const float4*>(A) + 2 * (size_t)i;
        float4 v0 = __ldcs(src), v1 = __ldcs(src + 1);
        __stcg(reinterpret_cast<uint4*>(g_Ah) + i, pack8(v0, v1));
    }
#pragma unroll 4
    for (size_t i = gid; i < (size_t)N * K / 8; i += nth) {
        const float4* src = reinterpret_cast<const float4*>(B) + 2 * i;
        float4 v0 = __ldcs(src), v1 = __ldcs(src + 1);
        __stcg(reinterpret_cast<uint4*>(g_Bh) + i, pack8(v0, v1));
    }
}

__global__ __launch_bounds__(256, 2)
void tl_gemm(const int* __restrict__ targets, const int* __restrict__ idxv,
             const int* __restrict__ labels, float* __restrict__ out)
{
    extern __shared__ __align__(1024) char smem[];
    __shared__ int      sT[BM];
    __shared__ int      sI[BM];
    __shared__ unsigned sPosU[BM];
    __shared__ unsigned sNegU[BM];
    __shared__ float    sRed[8];
    __shared__ unsigned sIsLast;

    const uint32_t sb = smem_u32(smem);
    const uint32_t sA = sb + OFF_A;
    const uint32_t sB = sb + OFF_B;
    int* sLab = (int*)(smem + OFF_LAB);

    const int tid  = threadIdx.x;
    const int lane = tid & 31;
    const int wid  = tid >> 5;
    const int rowBase = blockIdx.y * BM;
    const int colBase = blockIdx.x * BN;

    // 8 warps: 2 (m) x 4 (n); warp tile 64 x 64
    const int warp_m = (wid >> 2) * 64;
    const int warp_n = (wid & 3) * 64;

    for (int i = tid; i < BN; i += 256) sLab[i] = labels[colBase + i];
    if (tid < BM) {
        sT[tid] = targets[rowBase + tid];
        sI[tid] = idxv[rowBase + tid];
        sPosU[tid] = 0xFFFFFFFFu;
        sNegU[tid] = 0u;
    }

    auto load_stage = [&](int st, int c) {
        const int kb = c * BK;
        const uint32_t dA = sA + st * A_STAGE;
        const uint32_t dB = sB + st * B_STAGE;
#pragma unroll
        for (int i = 0; i < 4; ++i) {
            const int v = tid + i * 256;
            const int r = v >> 3, q = v & 7;
            cp_async16(dA + swz((uint32_t)(r * ROWB + q * 16)),
                       g_Ah + (size_t)(rowBase + r) * K + kb + q * 8);
        }
#pragma unroll
        for (int i = 0; i < 8; ++i) {
            const int v = tid + i * 256;
            const int r = v >> 3, q = v & 7;
            cp_async16(dB + swz((uint32_t)(r * ROWB + q * 16)),
                       g_Bh + (size_t)(colBase + r) * K + kb + q * 8);
        }
        cp_commit();
    };

    // Hoisted, pre-swizzled ldmatrix base addresses.
    // Identity: swz(base + ks*32) == swz(base) ^ (ks<<5)
    uint32_t aB[4], bB[4];
#pragma unroll
    for (int mi = 0; mi < 4; ++mi)
        aB[mi] = swz((uint32_t)(warp_m + (lane & 15) + mi * 16) * ROWB
                     + (lane >> 4) * 16);
#pragma unroll
    for (int g = 0; g < 4; ++g)
        bB[g] = swz((uint32_t)(warp_n + (lane & 7) + ((lane >> 4) & 1) * 8 + g * 16) * ROWB
                    + ((lane >> 3) & 1) * 16);

    uint32_t acc[4][8][2] = {};   // f16x2 accumulators

    load_stage(0, 0);             // prologue: only chunk 0

#pragma unroll 1
    for (int c = 0; c < NCH; ++c) {
        cp_wait<0>();
        __syncthreads();
        if (c + 1 < NCH) load_stage((c + 1) & 1, c + 1);

        const uint32_t stA = sA + (c & 1) * A_STAGE;
        const uint32_t stB = sB + (c & 1) * B_STAGE;
#pragma unroll
        for (int ks = 0; ks < 4; ++ks) {
            const uint32_t kx = (uint32_t)ks << 5;
            uint32_t af[4][4], bfr[4][4];
#pragma unroll
            for (int mi = 0; mi < 4; ++mi)
                ldsm_x4(af[mi], stA + (aB[mi] ^ kx));
#pragma unroll
            for (int g = 0; g < 4; ++g)
                ldsm_x4(bfr[g], stB + (bB[g] ^ kx));
#pragma unroll
            for (int mi = 0; mi < 4; ++mi)
#pragma unroll
                for (int ni = 0; ni < 8; ++ni)
                    mma_f16(acc[mi][ni], af[mi], &bfr[ni >> 1][(ni & 1) * 2]);
        }
    }
    __syncthreads();

    // Epilogue: unpack f16 acc, masked min/max with ordered-uint atomics.
    const int lq = lane >> 2;
    const int lr = (lane & 3) * 2;
#pragma unroll
    for (int mi = 0; mi < 4; ++mi) {
#pragma unroll
        for (int h = 0; h < 2; ++h) {
            const int rloc = warp_m + mi * 16 + h * 8 + lq;
            const int tg = sT[rloc];
            const int ix = sI[rloc];
            float pmin = f_inf(), nmax = f_ninf();
#pragma unroll
            for (int ni = 0; ni < 8; ++ni) {
                const float2 f2 = __half22float2(
                    *reinterpret_cast<const __half2*>(&acc[mi][ni][h]));
#pragma unroll
                for (int j = 0; j < 2; ++j) {
                    const int cloc = warp_n + ni * 8 + lr + j;
                    const float v = (j == 0) ? f2.x : f2.y;
                    if (sLab[cloc] == tg) {
                        if (colBase + cloc != ix) pmin = fminf(pmin, v);
                    } else {
                        nmax = fmaxf(nmax, v);
                    }
                }
            }
            if (pmin <  f_inf())  atomicMin(&sPosU[rloc], encOrd(pmin));
            if (nmax > f_ninf())  atomicMax(&sNegU[rloc], encOrd(nmax));
        }
    }
    __syncthreads();

    if (tid < BM) {
        const unsigned p = sPosU[tid], q = sNegU[tid];
        if (p != 0xFFFFFFFFu) atomicMin(&g_posU[rowBase + tid], p);
        if (q != 0u)          atomicMax(&g_negU[rowBase + tid], q);
    }

    // ---- fused finale ----
    __threadfence();
    if (tid == 0) {
        const unsigned total = gridDim.x * gridDim.y;
        sIsLast = (atomicAdd(&g_ctr, 1u) == total - 1u);
    }
    __syncthreads();
    if (!sIsLast) return;

    __threadfence();
    float l = 0.f;
#pragma unroll
    for (int r = 0; r < 4; ++r) {
        const int row = tid + r * 256;
        const float pos = decOrd(__ldcg(&g_posU[row]));
        const float neg = decOrd(__ldcg(&g_negU[row]));
        l += fmaxf(neg - pos + MARGIN, 0.0f);
    }
#pragma unroll
    for (int o = 16; o > 0; o >>= 1) l += __shfl_xor_sync(0xffffffffu, l, o);
    if (lane == 0) sRed[wid] = l;
    __syncthreads();
    if (tid < 8) {
        float s = sRed[tid];
#pragma unroll
        for (int o = 4; o > 0; o >>= 1) s += __shfl_xor_sync(0xffu, s, o);
        if (tid == 0) {
            out[0] = s * (1.0f / (float)M);
            g_ctr = 0;
        }
    }
}

extern "C" void kernel_launch(void* const* d_in, const int* in_sizes, int n_in,
                              void* d_out, int out_size) {
    const float* A       = (const float*)d_in[0];
    const float* B       = (const float*)d_in[1];
    const int*   targets = (const int*)  d_in[2];
    const int*   idxv    = (const int*)  d_in[3];
    const int*   labels  = (const int*)  d_in[4];
    float*       out     = (float*)d_out;

    static bool attrSet = false;
    if (!attrSet) {
        cudaFuncSetAttribute(tl_gemm, cudaFuncAttributeMaxDynamicSharedMemorySize,
                             SMEM_TOTAL);
        attrSet = true;
    }

    tl_quant<<<1536, 256>>>(A, B);
    dim3 grid(N / BN, M / BM);   // 128 x 8 = 1024 CTAs
    tl_gemm<<<grid, 256, SMEM_TOTAL>>>(targets, idxv, labels, out);
}